// round 2
// baseline (speedup 1.0000x reference)
#include <cuda_runtime.h>
#include <cstdint>

// Problem constants
#define NB   32
#define NN   4096
#define DM   64
#define DIN  65
#define MROWS (NB*DM)      // 2048
#define KDIM  (2*NN)       // 8192 (S=2 supports stacked into K)

// Scratch (device globals — allocation-free rule)
__device__ float g_Y[(size_t)MROWS * KDIM];   // 64 MiB, tf32-rounded, k-permuted
__device__ float g_G[(size_t)MROWS * NN];     // 32 MiB fp32

__device__ __forceinline__ uint32_t f2tf(float f) {
    uint32_t u; asm("cvt.rna.tf32.f32 %0, %1;" : "=r"(u) : "f"(f)); return u;
}

__device__ __forceinline__ void mma8(float* d,
    uint32_t a0, uint32_t a1, uint32_t a2, uint32_t a3, uint32_t b0, uint32_t b1) {
    asm volatile("mma.sync.aligned.m16n8k8.row.col.f32.tf32.tf32.f32 "
        "{%0,%1,%2,%3},{%4,%5,%6,%7},{%8,%9},{%0,%1,%2,%3};"
        : "+f"(d[0]), "+f"(d[1]), "+f"(d[2]), "+f"(d[3])
        : "r"(a0), "r"(a1), "r"(a2), "r"(a3), "r"(b0), "r"(b1));
}

__device__ __forceinline__ void cp16(uint32_t dst, const void* src) {
    asm volatile("cp.async.cg.shared.global [%0], [%1], 16;" :: "r"(dst), "l"(src));
}

// ---------------------------------------------------------------------------
// K1: Y[(b*64+m), s*4096+v] = Wmlp[m, s*65]*x[b,0,v] + sum_j Wmlp[m, s*65+1+j]*h[b,j,v]
// Stored tf32-rounded, with within-16-element 4x4 transpose permutation on k
// so K2 can fragment-load A with single LDS.128s.
// ---------------------------------------------------------------------------
__global__ void __launch_bounds__(128) k1_buildY(
    const float* __restrict__ x, const float* __restrict__ h,
    const float* __restrict__ Wmlp)
{
    __shared__ float sWh[128][64];
    __shared__ float sWx[128];
    const int tid = threadIdx.x;
    for (int o = tid; o < 128; o += 128) {
        int s = o >> 6, m = o & 63;
        sWx[o] = Wmlp[m * 130 + s * 65];
    }
    for (int idx = tid; idx < 128 * 64; idx += 128) {
        int o = idx >> 6, j = idx & 63;
        int s = o >> 6, m = o & 63;
        sWh[o][j] = Wmlp[m * 130 + s * 65 + 1 + j];
    }
    __syncthreads();

    const int b = blockIdx.y;
    const int v = blockIdx.x * 128 + tid;

    float hreg[64];
    const float* hb = h + (size_t)b * DM * NN + v;
#pragma unroll
    for (int j = 0; j < 64; j++) hreg[j] = hb[(size_t)j * NN];
    const float xv = x[(size_t)b * NN + v];

    const int vb = v & ~15;
    const int p  = ((v & 3) << 2) | ((v >> 2) & 3);   // 4x4 transpose within 16-block
    const size_t rowbase = (size_t)b * 64;

#pragma unroll 1
    for (int o = 0; o < 128; o++) {
        int s = o >> 6, m = o & 63;
        float acc = sWx[o] * xv;
        const float4* w4 = reinterpret_cast<const float4*>(sWh[o]);
#pragma unroll
        for (int q = 0; q < 16; q++) {
            float4 w = w4[q];
            acc += w.x * hreg[4*q] + w.y * hreg[4*q+1]
                 + w.z * hreg[4*q+2] + w.w * hreg[4*q+3];
        }
        g_Y[(rowbase + m) * KDIM + (size_t)s * NN + vb + p] = __uint_as_float(f2tf(acc));
    }
}

// ---------------------------------------------------------------------------
// K2: G[2048,4096] = Y[2048,8192] @ A[8192,4096],  A[(s,v), w] = adj[s, w, v]
// tf32 mma.sync, CTA tile 128x128x16, 4-stage cp.async pipeline.
// ---------------------------------------------------------------------------
#define STAGES 4
#define SA_ST  2048          // floats per A stage: 128 x 16
#define SB_ST  2560          // floats per B stage: 128 x 20 (padded)
#define K2_SMEM (STAGES * (SA_ST + SB_ST) * 4)

__global__ void __launch_bounds__(256, 2) k2_gemm(const float* __restrict__ adj)
{
    extern __shared__ float smem_dyn[];
    float* sA = smem_dyn;
    float* sB = smem_dyn + STAGES * SA_ST;

    const int tid  = threadIdx.x;
    const int bx   = blockIdx.x;          // n-tile (w)
    const int by   = blockIdx.y;          // m-tile ((b,m) rows)
    const int lane = tid & 31, warp = tid >> 5;
    const int wm = warp >> 2, wn = warp & 3;     // 2 x 4 warp grid
    const int g  = lane >> 2, t = lane & 3;

    const int r0 = tid >> 2, j0 = tid & 3;       // loader role: 2 rows x 1 chunk
    const float* Abase = g_Y + (size_t)(by * 128) * KDIM;
    const uint32_t sAu = (uint32_t)__cvta_generic_to_shared(sA);
    const uint32_t sBu = (uint32_t)__cvta_generic_to_shared(sB);

    float acc[4][4][4];
#pragma unroll
    for (int i = 0; i < 4; i++)
#pragma unroll
        for (int j = 0; j < 4; j++)
#pragma unroll
            for (int q = 0; q < 4; q++) acc[i][j][q] = 0.f;

    auto load_stage = [&](int st, int k) {
        const int kk = k << 4;
        const float* As = Abase + kk;
        uint32_t ad = sAu + (uint32_t)(st * SA_ST + r0 * 16 + j0 * 4) * 4u;
        cp16(ad,                 As + (size_t)r0        * KDIM + j0 * 4);
        cp16(ad + 64u * 16u * 4u, As + (size_t)(r0 + 64) * KDIM + j0 * 4);
        const int s = kk >> 12, v = kk & (NN - 1);
        const float* Bs = adj + (size_t)s * NN * NN + (size_t)(bx * 128) * NN + v;
        uint32_t bd = sBu + (uint32_t)(st * SB_ST + r0 * 20 + j0 * 4) * 4u;
        cp16(bd,                 Bs + (size_t)r0        * NN + j0 * 4);
        cp16(bd + 64u * 20u * 4u, Bs + (size_t)(r0 + 64) * NN + j0 * 4);
    };

    load_stage(0, 0); asm volatile("cp.async.commit_group;");
    load_stage(1, 1); asm volatile("cp.async.commit_group;");
    load_stage(2, 2); asm volatile("cp.async.commit_group;");

    const int NSTEP = KDIM / 16;   // 512
#pragma unroll 1
    for (int k = 0; k < NSTEP; k++) {
        asm volatile("cp.async.wait_group 2;");
        __syncthreads();
        const int st = k & 3;

        // B fragments: raw layout, scalar LDS (conflict-free via 20-float pad)
        uint32_t bU[4][2][2];
#pragma unroll
        for (int nt = 0; nt < 4; nt++) {
            const float* pb = sB + st * SB_ST + (wn * 32 + nt * 8 + g) * 20;
            bU[nt][0][0] = f2tf(pb[t]);
            bU[nt][0][1] = f2tf(pb[t + 4]);
            bU[nt][1][0] = f2tf(pb[t + 8]);
            bU[nt][1][1] = f2tf(pb[t + 12]);
        }
        // A fragments: permuted layout, one LDS.128 per 16-row group per slice-pair
#pragma unroll
        for (int mt = 0; mt < 4; mt++) {
            const float* pa = sA + st * SA_ST + (wm * 64 + mt * 16 + g) * 16 + t * 4;
            float4 lo = *reinterpret_cast<const float4*>(pa);
            float4 hi = *reinterpret_cast<const float4*>(pa + 128);  // +8 rows
            uint32_t a00 = __float_as_uint(lo.x), a10 = __float_as_uint(hi.x);
            uint32_t a20 = __float_as_uint(lo.y), a30 = __float_as_uint(hi.y);
            uint32_t a01 = __float_as_uint(lo.z), a11 = __float_as_uint(hi.z);
            uint32_t a21 = __float_as_uint(lo.w), a31 = __float_as_uint(hi.w);
#pragma unroll
            for (int nt = 0; nt < 4; nt++) {
                mma8(acc[mt][nt], a00, a10, a20, a30, bU[nt][0][0], bU[nt][0][1]);
                mma8(acc[mt][nt], a01, a11, a21, a31, bU[nt][1][0], bU[nt][1][1]);
            }
        }

        const int kn = k + (STAGES - 1);
        if (kn < NSTEP) load_stage(kn & 3, kn);
        asm volatile("cp.async.commit_group;");   // empty group in tail keeps wait semantics
    }

    // Store C tile -> g_G
#pragma unroll
    for (int mt = 0; mt < 4; mt++) {
        const int row = by * 128 + wm * 64 + mt * 16 + g;
#pragma unroll
        for (int nt = 0; nt < 4; nt++) {
            const int col = bx * 128 + wn * 32 + nt * 8 + 2 * t;
            float2 v0 = make_float2(acc[mt][nt][0], acc[mt][nt][1]);
            float2 v1 = make_float2(acc[mt][nt][2], acc[mt][nt][3]);
            *reinterpret_cast<float2*>(&g_G[(size_t)row       * NN + col]) = v0;
            *reinterpret_cast<float2*>(&g_G[(size_t)(row + 8) * NN + col]) = v1;
        }
    }
}

// ---------------------------------------------------------------------------
// K3: epilogue. Per (b,w): lin = Wlin @ [G+bmlp ; h] + blin ; pr = PReLU(lin)
// out2 = [pr ; h] ; read = Wread @ out2 + bread
// ---------------------------------------------------------------------------
__global__ void __launch_bounds__(256) k3_epi(
    const float* __restrict__ h,    const float* __restrict__ Wlin,
    const float* __restrict__ blin, const float* __restrict__ bmlp,
    const float* __restrict__ Wread,const float* __restrict__ bread,
    const float* __restrict__ pa,
    float* __restrict__ out_read,   float* __restrict__ out2)
{
    __shared__ float sWT[128][64];   // sWT[in][o] = Wlin[o,in]
    __shared__ float sWr[128];
    __shared__ float sbl[64];
    __shared__ float sbm[64];
    const int tid = threadIdx.x;
    for (int idx = tid; idx < 128 * 64; idx += 256) {
        int in = idx >> 6, o = idx & 63;
        sWT[in][o] = Wlin[o * 128 + in];
    }
    if (tid < 128) sWr[tid] = Wread[tid];
    if (tid < 64) { sbl[tid] = blin[tid]; sbm[tid] = bmlp[tid]; }
    __syncthreads();

    const int b = blockIdx.y;
    const int w = blockIdx.x * 256 + tid;

    float lin[64];
#pragma unroll
    for (int o = 0; o < 64; o++) lin[o] = sbl[o];
    float racc = __ldg(bread);
    const float a = __ldg(pa);

    const float* Gb = g_G + (size_t)b * 64 * NN + w;
    const float* hb = h    + (size_t)b * 64 * NN + w;
    float*       o2 = out2 + (size_t)b * 128 * NN + w;

#pragma unroll 1
    for (int m = 0; m < 64; m++) {
        float gv = Gb[(size_t)m * NN] + sbm[m];
        const float4* wrow = reinterpret_cast<const float4*>(sWT[m]);
#pragma unroll
        for (int q = 0; q < 16; q++) {
            float4 wv = wrow[q];
            lin[4*q]   += wv.x * gv; lin[4*q+1] += wv.y * gv;
            lin[4*q+2] += wv.z * gv; lin[4*q+3] += wv.w * gv;
        }
    }
#pragma unroll 1
    for (int j = 0; j < 64; j++) {
        float hv = hb[(size_t)j * NN];
        o2[(size_t)(64 + j) * NN] = hv;
        racc += sWr[64 + j] * hv;
        const float4* wrow = reinterpret_cast<const float4*>(sWT[64 + j]);
#pragma unroll
        for (int q = 0; q < 16; q++) {
            float4 wv = wrow[q];
            lin[4*q]   += wv.x * hv; lin[4*q+1] += wv.y * hv;
            lin[4*q+2] += wv.z * hv; lin[4*q+3] += wv.w * hv;
        }
    }
#pragma unroll
    for (int o = 0; o < 64; o++) {
        float pr = lin[o] >= 0.f ? lin[o] : a * lin[o];
        o2[(size_t)o * NN] = pr;
        racc += sWr[o] * pr;
    }
    out_read[(size_t)b * NN + w] = racc;
}

// ---------------------------------------------------------------------------
extern "C" void kernel_launch(void* const* d_in, const int* in_sizes, int n_in,
                              void* d_out, int out_size) {
    (void)in_sizes; (void)n_in; (void)out_size;
    const float* x     = (const float*)d_in[0];
    const float* h     = (const float*)d_in[1];
    const float* adj   = (const float*)d_in[2];
    const float* Wmlp  = (const float*)d_in[3];
    const float* bmlp  = (const float*)d_in[4];
    const float* Wlin  = (const float*)d_in[5];
    const float* blin  = (const float*)d_in[6];
    const float* Wread = (const float*)d_in[7];
    const float* bread = (const float*)d_in[8];
    const float* pa    = (const float*)d_in[9];

    float* out      = (float*)d_out;
    float* out_read = out;                       // [32, 1, 4096]
    float* out2     = out + (size_t)NB * NN;     // [32, 128, 4096]

    cudaFuncSetAttribute(k2_gemm, cudaFuncAttributeMaxDynamicSharedMemorySize, K2_SMEM);

    k1_buildY<<<dim3(NN / 128, NB), 128>>>(x, h, Wmlp);
    k2_gemm  <<<dim3(NN / 128, MROWS / 128), 256, K2_SMEM>>>(adj);
    k3_epi   <<<dim3(NN / 256, NB), 256>>>(h, Wlin, blin, bmlp, Wread, bread, pa,
                                           out_read, out2);
}

// round 6
// speedup vs baseline: 1.9131x; 1.9131x over previous
#include <cuda_runtime.h>
#include <cuda_bf16.h>
#include <cstdint>

// Problem constants
#define NB   32
#define NN   4096
#define DM   64
#define DIN  65
#define MROWS (NB*DM)      // 2048
#define KDIM  (2*NN)       // 8192

// Scratch (device globals — allocation-free rule)
__device__ __align__(1024) __nv_bfloat16 g_Yb[(size_t)MROWS * KDIM];  // 32 MiB
__device__ __align__(1024) __nv_bfloat16 g_adjb[(size_t)2 * NN * NN]; // 64 MiB
__device__ __align__(1024) float         g_G[(size_t)MROWS * NN];     // 32 MiB

// ---------------------------------------------------------------------------
// helpers
// ---------------------------------------------------------------------------
__device__ __forceinline__ uint32_t smem_u32(const void* p) {
    uint32_t a;
    asm("{ .reg .u64 t; cvta.to.shared.u64 t, %1; cvt.u32.u64 %0, t; }" : "=r"(a) : "l"(p));
    return a;
}
__device__ __forceinline__ void cp16(uint32_t dst, const void* src) {
    asm volatile("cp.async.cg.shared.global [%0], [%1], 16;" :: "r"(dst), "l"(src));
}
// SW128 swizzle for 128B rows: off ^ ((off>>3)&0x70)
__device__ __forceinline__ uint32_t sw128(uint32_t off) {
    return off ^ ((off >> 3) & 0x70);
}
__device__ __forceinline__ void ldsm4(uint32_t& r0, uint32_t& r1, uint32_t& r2,
                                      uint32_t& r3, uint32_t a) {
    asm volatile("ldmatrix.sync.aligned.m8n8.x4.shared.b16 {%0,%1,%2,%3}, [%4];"
        : "=r"(r0), "=r"(r1), "=r"(r2), "=r"(r3) : "r"(a));
}
__device__ __forceinline__ void mma16(float* d,
    uint32_t a0, uint32_t a1, uint32_t a2, uint32_t a3, uint32_t b0, uint32_t b1) {
    asm volatile("mma.sync.aligned.m16n8k16.row.col.f32.bf16.bf16.f32 "
        "{%0,%1,%2,%3},{%4,%5,%6,%7},{%8,%9},{%0,%1,%2,%3};"
        : "+f"(d[0]), "+f"(d[1]), "+f"(d[2]), "+f"(d[3])
        : "r"(a0), "r"(a1), "r"(a2), "r"(a3), "r"(b0), "r"(b1));
}

// ---------------------------------------------------------------------------
// K0: adj fp32 -> bf16 (g_adjb)
// ---------------------------------------------------------------------------
__global__ void __launch_bounds__(256) k0_conv(const float4* __restrict__ adj) {
    size_t i = (size_t)blockIdx.x * 256 + threadIdx.x;   // 8,388,608 float4s
    float4 v = adj[i];
    __nv_bfloat162 lo = __float22bfloat162_rn(make_float2(v.x, v.y));
    __nv_bfloat162 hi = __float22bfloat162_rn(make_float2(v.z, v.w));
    uint2 o;
    o.x = *reinterpret_cast<uint32_t*>(&lo);
    o.y = *reinterpret_cast<uint32_t*>(&hi);
    reinterpret_cast<uint2*>(g_adjb)[i] = o;
}

// ---------------------------------------------------------------------------
// K1: Y[(b*64+m), s*4096+v] (bf16, plain row-major)
// ---------------------------------------------------------------------------
__global__ void __launch_bounds__(128) k1_buildY(
    const float* __restrict__ x, const float* __restrict__ h,
    const float* __restrict__ Wmlp)
{
    __shared__ float sWh[128][64];
    __shared__ float sWx[128];
    const int tid = threadIdx.x;
    for (int o = tid; o < 128; o += 128) {
        int s = o >> 6, m = o & 63;
        sWx[o] = Wmlp[m * 130 + s * 65];
    }
    for (int idx = tid; idx < 128 * 64; idx += 128) {
        int o = idx >> 6, j = idx & 63;
        int s = o >> 6, m = o & 63;
        sWh[o][j] = Wmlp[m * 130 + s * 65 + 1 + j];
    }
    __syncthreads();

    const int b = blockIdx.y;
    const int v = blockIdx.x * 128 + tid;

    float hreg[64];
    const float* hb = h + (size_t)b * DM * NN + v;
#pragma unroll
    for (int j = 0; j < 64; j++) hreg[j] = hb[(size_t)j * NN];
    const float xv = x[(size_t)b * NN + v];
    const size_t rowbase = (size_t)b * 64;

#pragma unroll 1
    for (int o = 0; o < 128; o++) {
        int s = o >> 6, m = o & 63;
        float acc = sWx[o] * xv;
        const float4* w4 = reinterpret_cast<const float4*>(sWh[o]);
#pragma unroll
        for (int q = 0; q < 16; q++) {
            float4 w = w4[q];
            acc += w.x * hreg[4*q] + w.y * hreg[4*q+1]
                 + w.z * hreg[4*q+2] + w.w * hreg[4*q+3];
        }
        g_Yb[(rowbase + m) * KDIM + (size_t)s * NN + v] = __float2bfloat16_rn(acc);
    }
}

// ---------------------------------------------------------------------------
// K2: G[2048,4096] = Y @ A   (bf16 mma.sync.m16n8k16 + ldmatrix)
// CTA tile 128x128x64, 3-stage cp.async ring, 8 warps (2x4), warp tile 64x32.
// ---------------------------------------------------------------------------
#define STAGES      3
#define A_BYTES     16384           // 128 rows x 128B (k=64 bf16), SW128
#define B_BYTES     16384
#define STAGE_BYTES (A_BYTES + B_BYTES)
#define K2_SMEM     (STAGES * STAGE_BYTES)   // 98304

__global__ void __launch_bounds__(256, 2) k2_gemm()
{
    extern __shared__ char smem[];
    const uint32_t sbase = smem_u32(smem);
    const int tid  = threadIdx.x;
    const int lane = tid & 31, warp = tid >> 5;
    const int wm = warp >> 2, wn = warp & 3;        // 2 x 4 warp grid
    const int bx = blockIdx.x, by = blockIdx.y;
    const int m0 = by * 128, n0 = bx * 128;

    // fragment-load lane geometry (ldmatrix.x4, no trans; TN k-major tiles)
    const int alrow = (lane & 7) + ((lane >> 3) & 1) * 8;   // A: mats {m0-7,m8-15}x{k0,k16}
    const int akb   = (lane >> 4) * 16;
    const int blrow = (lane & 7) + ((lane >> 4) << 3);      // B: mats {n0-7}x{k0,k16},{n8-15}x{k0,k16}
    const int bkb   = ((lane >> 3) & 1) * 16;
    const int xorm  = (lane & 7) << 4;                      // swizzle XOR (row&7)<<4

    float acc[4][4][4];
#pragma unroll
    for (int i = 0; i < 4; i++)
#pragma unroll
        for (int j = 0; j < 4; j++)
#pragma unroll
            for (int q = 0; q < 4; q++) acc[i][j][q] = 0.f;

    auto load_stage = [&](int st, int k) {
        const int k0 = k << 6;
        const int ssel = k0 >> 12, kv = k0 & (NN - 1);
        const uint32_t abase = sbase + st * STAGE_BYTES;
        const uint32_t bbase = abase + A_BYTES;
#pragma unroll
        for (int i = 0; i < 4; i++) {                  // A: 128 rows x 8 x 16B
            int c = i * 256 + tid;
            int row = c >> 3, col = c & 7;
            cp16(abase + sw128(row * 128 + col * 16),
                 g_Yb + (size_t)(m0 + row) * KDIM + k0 + col * 8);
        }
#pragma unroll
        for (int i = 0; i < 4; i++) {                  // B: 128 rows x 8 x 16B
            int c = i * 256 + tid;
            int row = c >> 3, col = c & 7;
            cp16(bbase + sw128(row * 128 + col * 16),
                 g_adjb + (size_t)ssel * NN * NN + (size_t)(n0 + row) * NN + kv + col * 8);
        }
    };

    load_stage(0, 0); asm volatile("cp.async.commit_group;");
    load_stage(1, 1); asm volatile("cp.async.commit_group;");

    const int NSTEP = KDIM / 64;   // 128
#pragma unroll 1
    for (int k = 0; k < NSTEP; k++) {
        asm volatile("cp.async.wait_group 1;");
        __syncthreads();
        const int st = k % STAGES;
        const uint32_t sA = sbase + st * STAGE_BYTES;
        const uint32_t sB = sA + A_BYTES;
        const uint32_t aBase = sA + (uint32_t)(wm * 64 + alrow) * 128;
        const uint32_t bBase = sB + (uint32_t)(wn * 32 + blrow) * 128;

#pragma unroll
        for (int ks = 0; ks < 4; ks++) {
            const int kb = ks * 32;
            uint32_t bf[4][2];
#pragma unroll
            for (int j = 0; j < 2; j++) {
                uint32_t r0, r1, r2, r3;
                ldsm4(r0, r1, r2, r3,
                      bBase + (uint32_t)(j * 16) * 128 + ((kb + bkb) ^ xorm));
                bf[2*j][0] = r0;   bf[2*j][1] = r1;
                bf[2*j+1][0] = r2; bf[2*j+1][1] = r3;
            }
#pragma unroll
            for (int mt = 0; mt < 4; mt++) {
                uint32_t a0, a1, a2, a3;
                ldsm4(a0, a1, a2, a3,
                      aBase + (uint32_t)(mt * 16) * 128 + ((kb + akb) ^ xorm));
#pragma unroll
                for (int nt = 0; nt < 4; nt++)
                    mma16(acc[mt][nt], a0, a1, a2, a3, bf[nt][0], bf[nt][1]);
            }
        }

        __syncthreads();
        const int kn = k + 2;
        if (kn < NSTEP) load_stage(kn % STAGES, kn);
        asm volatile("cp.async.commit_group;");   // empty group in tail keeps semantics
    }

    // Store C tile -> g_G
    const int g = lane >> 2, t = lane & 3;
#pragma unroll
    for (int mt = 0; mt < 4; mt++) {
        const int row = m0 + wm * 64 + mt * 16 + g;
#pragma unroll
        for (int nt = 0; nt < 4; nt++) {
            const int col = n0 + wn * 32 + nt * 8 + 2 * t;
            float2 v0 = make_float2(acc[mt][nt][0], acc[mt][nt][1]);
            float2 v1 = make_float2(acc[mt][nt][2], acc[mt][nt][3]);
            *reinterpret_cast<float2*>(&g_G[(size_t)row       * NN + col]) = v0;
            *reinterpret_cast<float2*>(&g_G[(size_t)(row + 8) * NN + col]) = v1;
        }
    }
}

// ---------------------------------------------------------------------------
// K3: epilogue. Per (b,w): lin = Wlin @ [G+bmlp ; h] + blin ; PReLU ; out2 ; read
// ---------------------------------------------------------------------------
__global__ void __launch_bounds__(256) k3_epi(
    const float* __restrict__ h,    const float* __restrict__ Wlin,
    const float* __restrict__ blin, const float* __restrict__ bmlp,
    const float* __restrict__ Wread,const float* __restrict__ bread,
    const float* __restrict__ pa,
    float* __restrict__ out_read,   float* __restrict__ out2)
{
    __shared__ float sWT[128][64];   // sWT[in][o] = Wlin[o,in]
    __shared__ float sWr[128];
    __shared__ float sbl[64];
    __shared__ float sbm[64];
    const int tid = threadIdx.x;
    for (int idx = tid; idx < 128 * 64; idx += 256) {
        int in = idx >> 6, o = idx & 63;
        sWT[in][o] = Wlin[o * 128 + in];
    }
    if (tid < 128) sWr[tid] = Wread[tid];
    if (tid < 64) { sbl[tid] = blin[tid]; sbm[tid] = bmlp[tid]; }
    __syncthreads();

    const int b = blockIdx.y;
    const int w = blockIdx.x * 256 + tid;

    float lin[64];
#pragma unroll
    for (int o = 0; o < 64; o++) lin[o] = sbl[o];
    float racc = __ldg(bread);
    const float a = __ldg(pa);

    const float* Gb = g_G + (size_t)b * 64 * NN + w;
    const float* hb = h    + (size_t)b * 64 * NN + w;
    float*       o2 = out2 + (size_t)b * 128 * NN + w;

#pragma unroll 1
    for (int m = 0; m < 64; m++) {
        float gv = Gb[(size_t)m * NN] + sbm[m];
        const float4* wrow = reinterpret_cast<const float4*>(sWT[m]);
#pragma unroll
        for (int q = 0; q < 16; q++) {
            float4 wv = wrow[q];
            lin[4*q]   += wv.x * gv; lin[4*q+1] += wv.y * gv;
            lin[4*q+2] += wv.z * gv; lin[4*q+3] += wv.w * gv;
        }
    }
#pragma unroll 1
    for (int j = 0; j < 64; j++) {
        float hv = hb[(size_t)j * NN];
        o2[(size_t)(64 + j) * NN] = hv;
        racc += sWr[64 + j] * hv;
        const float4* wrow = reinterpret_cast<const float4*>(sWT[64 + j]);
#pragma unroll
        for (int q = 0; q < 16; q++) {
            float4 wv = wrow[q];
            lin[4*q]   += wv.x * hv; lin[4*q+1] += wv.y * hv;
            lin[4*q+2] += wv.z * hv; lin[4*q+3] += wv.w * hv;
        }
    }
#pragma unroll
    for (int o = 0; o < 64; o++) {
        float pr = lin[o] >= 0.f ? lin[o] : a * lin[o];
        o2[(size_t)o * NN] = pr;
        racc += sWr[o] * pr;
    }
    out_read[(size_t)b * NN + w] = racc;
}

// ---------------------------------------------------------------------------
extern "C" void kernel_launch(void* const* d_in, const int* in_sizes, int n_in,
                              void* d_out, int out_size) {
    (void)in_sizes; (void)n_in; (void)out_size;
    const float* x     = (const float*)d_in[0];
    const float* h     = (const float*)d_in[1];
    const float* adj   = (const float*)d_in[2];
    const float* Wmlp  = (const float*)d_in[3];
    const float* bmlp  = (const float*)d_in[4];
    const float* Wlin  = (const float*)d_in[5];
    const float* blin  = (const float*)d_in[6];
    const float* Wread = (const float*)d_in[7];
    const float* bread = (const float*)d_in[8];
    const float* pa    = (const float*)d_in[9];

    float* out      = (float*)d_out;
    float* out_read = out;                       // [32, 1, 4096]
    float* out2     = out + (size_t)NB * NN;     // [32, 128, 4096]

    cudaFuncSetAttribute(k2_gemm, cudaFuncAttributeMaxDynamicSharedMemorySize, K2_SMEM);

    k0_conv  <<<32768, 256>>>((const float4*)adj);
    k1_buildY<<<dim3(NN / 128, NB), 128>>>(x, h, Wmlp);
    k2_gemm  <<<dim3(NN / 128, MROWS / 128), 256, K2_SMEM>>>();
    k3_epi   <<<dim3(NN / 256, NB), 256>>>(h, Wlin, blin, bmlp, Wread, bread, pa,
                                           out_read, out2);
}